// round 2
// baseline (speedup 1.0000x reference)
#include <cuda_runtime.h>
#include <math.h>

#define Bn 32
#define Cn 20
#define Sn 65536
#define Mn 16
#define Qn 4096
#define Hn 128

// Scratch (device globals; allocation-free rule)
__device__ float  g_h[(size_t)Bn * Cn * Sn];          // (B, C, S) ~168MB
__device__ float  g_partR[Bn][Cn][2][Mn];
__device__ float  g_partI[Bn][Cn][2][Mn];
__device__ float2 g_coef[Bn][Cn][Mn];
__device__ float  g_maxv;

__device__ __forceinline__ float gelu_exact(float x) {
    return 0.5f * x * (1.0f + erff(x * 0.7071067811865476f));
}

// ------------------------------------------------------------------ max
__global__ void fno_kmax(const float* __restrict__ p) {
    __shared__ float sm[1024];
    float m = -1e30f;
    for (int i = threadIdx.x; i < Sn; i += 1024) m = fmaxf(m, p[i]);
    sm[threadIdx.x] = m;
    __syncthreads();
    for (int off = 512; off; off >>= 1) {
        if (threadIdx.x < off) sm[threadIdx.x] = fmaxf(sm[threadIdx.x], sm[threadIdx.x + off]);
        __syncthreads();
    }
    if (threadIdx.x == 0) g_maxv = sm[0];
}

// ------------------------------------------------------------------ fc0
__global__ void __launch_bounds__(256) fno_kfc0(const float* __restrict__ x,
                                                const float* __restrict__ p,
                                                const float* __restrict__ w,
                                                const float* __restrict__ bias) {
    const int s = blockIdx.x * 256 + threadIdx.x;
    const int b = blockIdx.y;
    const float xv = x[(size_t)b * Sn + s];
    const float gv = p[s] / g_maxv;
#pragma unroll
    for (int c = 0; c < Cn; c++) {
        g_h[((size_t)(b * Cn + c)) * Sn + s] = fmaf(xv, w[c], fmaf(gv, w[Cn + c], bias[c]));
    }
}

// --------------------------------------------- forward truncated DFT (16 modes)
// F_k = sum_q z_q^k * B_k[q],  B_k[q] = 16-pt DFT over p of h[q + 4096 p]
__global__ void __launch_bounds__(256) fno_kfwd() {
    const int qc = blockIdx.x;   // 0..1
    const int c  = blockIdx.y;   // 0..19
    const int b  = blockIdx.z;   // 0..31
    const float* __restrict__ row = g_h + ((size_t)(b * Cn + c)) * Sn;
    const int tid = threadIdx.x;
    const int q0 = qc * 2048 + tid;

    float Fr[Mn], Fi[Mn];
#pragma unroll
    for (int k = 0; k < Mn; k++) { Fr[k] = 0.f; Fi[k] = 0.f; }

    // z = e^{-2 pi i q0 / 65536}
    float zr, zi;
    sincospif(-(float)q0 * (1.0f / 32768.0f), &zi, &zr);
    const float Rr =  0.9996988186962042f;    // cos(2pi*256/65536)
    const float Ri = -0.0245412285229123f;    // -sin(2pi*256/65536)

    const float C16[16] = { 1.f,  0.9238795325112867f,  0.7071067811865476f,  0.3826834323650898f,
                            0.f, -0.3826834323650898f, -0.7071067811865476f, -0.9238795325112867f,
                           -1.f, -0.9238795325112867f, -0.7071067811865476f, -0.3826834323650898f,
                            0.f,  0.3826834323650898f,  0.7071067811865476f,  0.9238795325112867f };
    const float S16[16] = { 0.f,  0.3826834323650898f,  0.7071067811865476f,  0.9238795325112867f,
                            1.f,  0.9238795325112867f,  0.7071067811865476f,  0.3826834323650898f,
                            0.f, -0.3826834323650898f, -0.7071067811865476f, -0.9238795325112867f,
                           -1.f, -0.9238795325112867f, -0.7071067811865476f, -0.3826834323650898f };

    for (int it = 0; it < 8; ++it) {
        const int q = q0 + it * 256;
        float hp[16];
#pragma unroll
        for (int p = 0; p < 16; p++) hp[p] = row[q + p * Qn];

        float u[8], dd[8];
#pragma unroll
        for (int p = 0; p < 8; p++) { u[p] = hp[p] + hp[p + 8]; dd[p] = hp[p] - hp[p + 8]; }

        float BR[16], BI[16];
        // even bins 0,2,4,6,8 from u
#pragma unroll
        for (int j = 0; j <= 4; j++) {
            float ar = 0.f, ai = 0.f;
#pragma unroll
            for (int p = 0; p < 8; p++) {
                const int m = (2 * j * p) & 15;
                ar += u[p] * C16[m];
                ai -= u[p] * S16[m];
            }
            BR[2 * j] = ar; BI[2 * j] = ai;
        }
        // odd bins 1,3,5,7 from dd
#pragma unroll
        for (int k = 1; k < 8; k += 2) {
            float ar = 0.f, ai = 0.f;
#pragma unroll
            for (int p = 0; p < 8; p++) {
                const int m = (k * p) & 15;
                ar += dd[p] * C16[m];
                ai -= dd[p] * S16[m];
            }
            BR[k] = ar; BI[k] = ai;
        }
        // hermitian mirror (real input)
#pragma unroll
        for (int k = 9; k < 16; k++) { BR[k] = BR[16 - k]; BI[k] = -BI[16 - k]; }

        // F_k += B_k * z^k
        Fr[0] += BR[0];
        Fi[0] += BI[0];
        float wr = zr, wi = zi;
#pragma unroll
        for (int k = 1; k < 16; k++) {
            Fr[k] += BR[k] * wr - BI[k] * wi;
            Fi[k] += BR[k] * wi + BI[k] * wr;
            const float nwr = wr * zr - wi * zi;
            const float nwi = wr * zi + wi * zr;
            wr = nwr; wi = nwi;
        }
        const float nzr = zr * Rr - zi * Ri;
        const float nzi = zr * Ri + zi * Rr;
        zr = nzr; zi = nzi;
    }

    // deterministic reduction: warp shuffle -> shared -> first 16 threads
#pragma unroll
    for (int off = 16; off; off >>= 1) {
#pragma unroll
        for (int k = 0; k < Mn; k++) {
            Fr[k] += __shfl_down_sync(0xffffffffu, Fr[k], off);
            Fi[k] += __shfl_down_sync(0xffffffffu, Fi[k], off);
        }
    }
    __shared__ float redR[8][Mn], redI[8][Mn];
    const int warp = tid >> 5, lane = tid & 31;
    if (lane == 0) {
#pragma unroll
        for (int k = 0; k < Mn; k++) { redR[warp][k] = Fr[k]; redI[warp][k] = Fi[k]; }
    }
    __syncthreads();
    if (tid < Mn) {
        float ar = 0.f, ai = 0.f;
#pragma unroll
        for (int w = 0; w < 8; w++) { ar += redR[w][tid]; ai += redI[w][tid]; }
        g_partR[b][c][qc][tid] = ar;
        g_partI[b][c][qc][tid] = ai;
    }
}

// ------------------------------------------------------------------ mode mixing
__global__ void fno_kmix(const float* __restrict__ sre, const float* __restrict__ sim) {
    const int b = blockIdx.x;
    const int tid = threadIdx.x;          // 320 threads: o*16 + k
    const int o = tid >> 4, k = tid & 15;
    float Gr = 0.f, Gi = 0.f;
#pragma unroll
    for (int i = 0; i < Cn; i++) {
        const float fr = g_partR[b][i][0][k] + g_partR[b][i][1][k];
        const float fi = g_partI[b][i][0][k] + g_partI[b][i][1][k];
        const float wr = sre[i * (Cn * Mn) + o * Mn + k];
        const float wi = sim[i * (Cn * Mn) + o * Mn + k];
        Gr += fr * wr - fi * wi;
        Gi += fr * wi + fi * wr;
    }
    const float invS = 1.0f / (float)Sn;
    float2 cf;
    if (k == 0) { cf.x = Gr * invS; cf.y = 0.f; }        // irfft drops DC imag
    else        { cf.x = 2.f * Gr * invS; cf.y = 2.f * Gi * invS; }
    g_coef[b][o][k] = cf;
}

// ------------------------------------- inverse + 1x1 conv + gelu (layers 0..2)
__global__ void __launch_bounds__(256) fno_kinv(const float* __restrict__ ww,
                                                const float* __restrict__ wb) {
    __shared__ float2 s_coef[Cn][Mn];
    __shared__ float  s_ww[Cn * Cn];
    __shared__ float  s_wb[Cn];
    const int b = blockIdx.y;
    const int tid = threadIdx.x;
    for (int i = tid; i < Cn * Mn; i += 256) s_coef[i / Mn][i % Mn] = g_coef[b][i / Mn][i % Mn];
    for (int i = tid; i < Cn * Cn; i += 256) s_ww[i] = ww[i];
    if (tid < Cn) s_wb[tid] = wb[tid];
    __syncthreads();

    const int s = blockIdx.x * 256 + tid;
    float co, si;
    sincospif((float)s * (1.0f / 32768.0f), &si, &co);   // e^{+2pi i s/S}
    float cs[Mn], sn[Mn];
    {
        float wr = co, wi = si;
#pragma unroll
        for (int k = 1; k < Mn; k++) {
            cs[k] = wr; sn[k] = wi;
            const float nr = wr * co - wi * si;
            const float ni = wr * si + wi * co;
            wr = nr; wi = ni;
        }
    }
    float hv[Cn];
#pragma unroll
    for (int c = 0; c < Cn; c++) hv[c] = g_h[((size_t)(b * Cn + c)) * Sn + s];

    float outv[Cn];
#pragma unroll
    for (int o = 0; o < Cn; o++) {
        float acc = s_coef[o][0].x + s_wb[o];
#pragma unroll
        for (int k = 1; k < Mn; k++) {
            const float2 cc = s_coef[o][k];
            acc += cc.x * cs[k] - cc.y * sn[k];
        }
#pragma unroll
        for (int c = 0; c < Cn; c++) acc += hv[c] * s_ww[o * Cn + c];
        outv[o] = gelu_exact(acc);
    }
#pragma unroll
    for (int o = 0; o < Cn; o++) g_h[((size_t)(b * Cn + o)) * Sn + s] = outv[o];
}

// ---------- final: layer-3 inverse+conv (no gelu) -> fc1 -> gelu -> fc2 -------
__global__ void __launch_bounds__(256) fno_kfinal(const float* __restrict__ ww,
                                                  const float* __restrict__ wb,
                                                  const float* __restrict__ fc1w,
                                                  const float* __restrict__ fc1b,
                                                  const float* __restrict__ fc2w,
                                                  const float* __restrict__ fc2b,
                                                  float* __restrict__ out) {
    __shared__ float2 s_coef[Cn][Mn];
    __shared__ float  s_ww[Cn * Cn];
    __shared__ float  s_wb[Cn];
    __shared__ float4 s_fc1[Cn][Hn / 4];
    __shared__ float4 s_fc1b[Hn / 4];
    __shared__ float4 s_fc2[Hn / 4];
    const int b = blockIdx.y;
    const int tid = threadIdx.x;
    for (int i = tid; i < Cn * Mn; i += 256) s_coef[i / Mn][i % Mn] = g_coef[b][i / Mn][i % Mn];
    for (int i = tid; i < Cn * Cn; i += 256) s_ww[i] = ww[i];
    if (tid < Cn) s_wb[tid] = wb[tid];
    for (int i = tid; i < Cn * (Hn / 4); i += 256) {
        const int c = i / (Hn / 4), h4 = i % (Hn / 4);
        s_fc1[c][h4] = make_float4(fc1w[c * Hn + 4 * h4 + 0], fc1w[c * Hn + 4 * h4 + 1],
                                   fc1w[c * Hn + 4 * h4 + 2], fc1w[c * Hn + 4 * h4 + 3]);
    }
    if (tid < Hn / 4) {
        s_fc1b[tid] = make_float4(fc1b[4 * tid], fc1b[4 * tid + 1], fc1b[4 * tid + 2], fc1b[4 * tid + 3]);
        s_fc2[tid]  = make_float4(fc2w[4 * tid], fc2w[4 * tid + 1], fc2w[4 * tid + 2], fc2w[4 * tid + 3]);
    }
    __syncthreads();

    const int s = blockIdx.x * 256 + tid;
    float co, si;
    sincospif((float)s * (1.0f / 32768.0f), &si, &co);
    float cs[Mn], sn[Mn];
    {
        float wr = co, wi = si;
#pragma unroll
        for (int k = 1; k < Mn; k++) {
            cs[k] = wr; sn[k] = wi;
            const float nr = wr * co - wi * si;
            const float ni = wr * si + wi * co;
            wr = nr; wi = ni;
        }
    }
    float t[Cn];
#pragma unroll
    for (int c = 0; c < Cn; c++) t[c] = g_h[((size_t)(b * Cn + c)) * Sn + s];

    float to[Cn];
#pragma unroll
    for (int o = 0; o < Cn; o++) {
        float acc = s_coef[o][0].x + s_wb[o];
#pragma unroll
        for (int k = 1; k < Mn; k++) {
            const float2 cc = s_coef[o][k];
            acc += cc.x * cs[k] - cc.y * sn[k];
        }
#pragma unroll
        for (int c = 0; c < Cn; c++) acc += t[c] * s_ww[o * Cn + c];
        to[o] = acc;                       // layer 3: NO gelu
    }

    float res = fc2b[0];
#pragma unroll 4
    for (int h4 = 0; h4 < Hn / 4; h4++) {
        float4 a = s_fc1b[h4];
#pragma unroll
        for (int c = 0; c < Cn; c++) {
            const float4 w4 = s_fc1[c][h4];
            a.x = fmaf(to[c], w4.x, a.x);
            a.y = fmaf(to[c], w4.y, a.y);
            a.z = fmaf(to[c], w4.z, a.z);
            a.w = fmaf(to[c], w4.w, a.w);
        }
        const float4 f2 = s_fc2[h4];
        res += gelu_exact(a.x) * f2.x + gelu_exact(a.y) * f2.y
             + gelu_exact(a.z) * f2.z + gelu_exact(a.w) * f2.w;
    }
    out[(size_t)b * Sn + s] = res;
}

// ------------------------------------------------------------------ launch
extern "C" void kernel_launch(void* const* d_in, const int* in_sizes, int n_in,
                              void* d_out, int out_size) {
    const float* x  = (const float*)d_in[0];
    const float* pd = (const float*)d_in[1];
    const float* fc0w = (const float*)d_in[2];
    const float* fc0b = (const float*)d_in[3];
    const float *fc1w, *fc1b, *fc2w, *fc2b;
    const float *sre[4], *sim[4], *lww[4], *lwb[4];

    if (in_sizes[4] == Cn * Hn) {
        // dict order: fc1, fc2 next, then per-layer groups
        fc1w = (const float*)d_in[4]; fc1b = (const float*)d_in[5];
        fc2w = (const float*)d_in[6]; fc2b = (const float*)d_in[7];
        for (int l = 0; l < 4; l++) {
            sre[l] = (const float*)d_in[8 + 4 * l];
            sim[l] = (const float*)d_in[9 + 4 * l];
            lww[l] = (const float*)d_in[10 + 4 * l];
            lwb[l] = (const float*)d_in[11 + 4 * l];
        }
    } else {
        // signature order: per-layer groups, then fc1/fc2
        for (int l = 0; l < 4; l++) {
            sre[l] = (const float*)d_in[4 + 4 * l];
            sim[l] = (const float*)d_in[5 + 4 * l];
            lww[l] = (const float*)d_in[6 + 4 * l];
            lwb[l] = (const float*)d_in[7 + 4 * l];
        }
        fc1w = (const float*)d_in[20]; fc1b = (const float*)d_in[21];
        fc2w = (const float*)d_in[22]; fc2b = (const float*)d_in[23];
    }

    float* out = (float*)d_out;
    const dim3 gS(Sn / 256, Bn);

    fno_kmax<<<1, 1024>>>(pd);
    fno_kfc0<<<gS, 256>>>(x, pd, fc0w, fc0b);

    for (int l = 0; l < 3; l++) {
        fno_kfwd<<<dim3(2, Cn, Bn), 256>>>();
        fno_kmix<<<Bn, Cn * Mn>>>(sre[l], sim[l]);
        fno_kinv<<<gS, 256>>>(lww[l], lwb[l]);
    }
    fno_kfwd<<<dim3(2, Cn, Bn), 256>>>();
    fno_kmix<<<Bn, Cn * Mn>>>(sre[3], sim[3]);
    fno_kfinal<<<gS, 256>>>(lww[3], lwb[3], fc1w, fc1b, fc2w, fc2b, out);
}